// round 2
// baseline (speedup 1.0000x reference)
#include <cuda_runtime.h>
#include <cuda_bf16.h>
#include <math.h>

// Problem sizes (fixed by setup_inputs)
#define NS 512     // samples
#define AD 2048    // feature dim
#define CC 1000    // classes

// Output layout: loss(1) | y(512*1000) | new_ave(1000*2048) | new_cov(1000*2048) | new_amount(1000)
#define OFF_Y    1
#define OFF_AVE  (1 + NS*CC)                // 512001
#define OFF_COV  (OFF_AVE + CC*AD)          // 2560001
#define OFF_AMT  (OFF_COV + CC*AD)          // 4608001

// Scratch (device globals; no allocations allowed)
__device__ float g_counts[CC];
__device__ float g_sums[CC*AD];   // becomes ave_CxA after k_ave
__device__ float g_sq[CC*AD];     // sq-diff sums; after k_fin: aligned copy of new_cov
__device__ float g_cvn[NS*AD];    // new_cov gathered by label
__device__ float g_wcv[NS*AD];    // w_n * cv_n
__device__ float g_t3[NS];
__device__ float g_isda[NS*CC];

// ---------------------------------------------------------------- zero init
__global__ void k_zero(float* d_out) {
    long gid = (long)blockIdx.x * blockDim.x + threadIdx.x;
    if (gid < (long)CC*AD) { g_sums[gid] = 0.f; g_sq[gid] = 0.f; }
    if (gid < CC) g_counts[gid] = 0.f;
    if (gid == 0) d_out[0] = 0.f;
}

// ------------------------------------------------- counts + per-class sums
__global__ void k_sums(const float* __restrict__ f, const int* __restrict__ labels) {
    int i = blockIdx.x;
    int l = labels[i];
    if (threadIdx.x == 0) atomicAdd(&g_counts[l], 1.0f);
    const float4* fr = (const float4*)(f + (size_t)i * AD);
    float* dst = g_sums + (size_t)l * AD;
    for (int v = threadIdx.x; v < AD/4; v += blockDim.x) {
        float4 x = fr[v];
        atomicAdd(dst + 4*v + 0, x.x);
        atomicAdd(dst + 4*v + 1, x.y);
        atomicAdd(dst + 4*v + 2, x.z);
        atomicAdd(dst + 4*v + 3, x.w);
    }
}

// ------------------------------------------------- ave_CxA = sums / denom
__global__ void k_ave() {
    long gid = (long)blockIdx.x * blockDim.x + threadIdx.x;
    if (gid >= (long)CC*AD) return;
    int c = (int)(gid / AD);
    float cnt = g_counts[c];
    float den = (cnt == 0.f) ? 1.f : cnt;
    g_sums[gid] = g_sums[gid] / den;
}

// ------------------------------------------------- squared-diff segment sum
__global__ void k_sq(const float* __restrict__ f, const int* __restrict__ labels) {
    int i = blockIdx.x;
    int l = labels[i];
    const float4* fr = (const float4*)(f + (size_t)i * AD);
    const float4* av = (const float4*)(g_sums + (size_t)l * AD);
    float* dst = g_sq + (size_t)l * AD;
    for (int v = threadIdx.x; v < AD/4; v += blockDim.x) {
        float4 x = fr[v];
        float4 a = av[v];
        float dx = x.x - a.x, dy = x.y - a.y, dz = x.z - a.z, dw = x.w - a.w;
        atomicAdd(dst + 4*v + 0, dx*dx);
        atomicAdd(dst + 4*v + 1, dy*dy);
        atomicAdd(dst + 4*v + 2, dz*dz);
        atomicAdd(dst + 4*v + 3, dw*dw);
    }
}

// ------------------------------------------------- finalize ave/cov/amount
// Also writes new_cov into g_sq (aligned scratch) for the gather kernel,
// because d_out+OFF_COV is an odd float offset (not 16B-aligned).
__global__ void k_fin(const float* __restrict__ ave_in, const float* __restrict__ cov_in,
                      const float* __restrict__ amt_in, float* __restrict__ d_out) {
    long gid = (long)blockIdx.x * blockDim.x + threadIdx.x;
    if (gid >= (long)CC*AD) return;
    int c = (int)(gid / AD);
    float cnt = g_counts[c];
    float amt = amt_in[c];
    float den = cnt + amt;
    float w = (den > 0.f) ? (cnt / den) : 0.f;   // nan_to_num(counts/(counts+amount))
    float vden = (cnt == 0.f) ? 1.f : cnt;
    float aveC = g_sums[gid];
    float var  = g_sq[gid] / vden;
    float a0   = ave_in[gid];
    float c0   = cov_in[gid];
    float d    = a0 - aveC;
    float addl = w * (1.f - w) * d * d;
    float ncov = c0 * (1.f - w) + var * w + addl;
    d_out[OFF_COV + gid] = ncov;
    g_sq[gid] = ncov;                    // aligned copy for k_gather
    d_out[OFF_AVE + gid] = a0 * (1.f - w) + aveC * w;
    if (gid < CC) d_out[OFF_AMT + gid] = amt_in[gid] + g_counts[gid];
}

// ------------------------------------------------- gather cv_n, w_n*cv_n, t3
__global__ void k_gather(const float* __restrict__ W, const int* __restrict__ labels) {
    __shared__ float sh[256];
    int i = blockIdx.x;
    int l = labels[i];
    const float4* cvr = (const float4*)(g_sq + (size_t)l * AD);   // new_cov (aligned)
    const float4* wr  = (const float4*)(W + (size_t)l * AD);
    float4* cvd = (float4*)(g_cvn + (size_t)i * AD);
    float4* wcd = (float4*)(g_wcv + (size_t)i * AD);
    float acc = 0.f;
    for (int v = threadIdx.x; v < AD/4; v += blockDim.x) {
        float4 cv = cvr[v];
        float4 w  = wr[v];
        cvd[v] = cv;
        float4 wc = make_float4(w.x*cv.x, w.y*cv.y, w.z*cv.z, w.w*cv.w);
        wcd[v] = wc;
        acc += w.x*wc.x + w.y*wc.y + w.z*wc.z + w.w*wc.w;  // w^2 * cv
    }
    sh[threadIdx.x] = acc;
    __syncthreads();
    for (int s = 128; s > 0; s >>= 1) {
        if (threadIdx.x < s) sh[threadIdx.x] += sh[threadIdx.x + s];
        __syncthreads();
    }
    if (threadIdx.x == 0) g_t3[i] = sh[0];
}

// ------------------------------------------------- fused triple GEMM
// y[i,j]   = sum_k F[i,k]*W[j,k] + bias[j]
// t1[i,j]  = sum_k cvn[i,k]*W[j,k]^2
// t2[i,j]  = sum_k wcv[i,k]*W[j,k]
// isda     = y + 0.5*ratio*(t1 - 2*t2 + t3[i])
#define BM 64
#define BN 64
#define BK 8
__global__ __launch_bounds__(256) void k_gemm(
    const float* __restrict__ F, const float* __restrict__ W,
    const float* __restrict__ bias, const int* __restrict__ ratio_bits,
    float* __restrict__ d_out)
{
    __shared__ float sF[BK][BM], sC[BK][BM], sWc[BK][BM], sB[BK][BN];
    int tid = threadIdx.x;
    int tx = tid & 15, ty = tid >> 4;
    int j0 = blockIdx.x * BN, i0 = blockIdx.y * BM;

    float ay[4][4] = {}, a1[4][4] = {}, a2[4][4] = {};

    for (int k0 = 0; k0 < AD; k0 += BK) {
        __syncthreads();
        #pragma unroll
        for (int r = 0; r < 2; r++) {
            int slot = tid + 256 * r;           // 0..511
            int tile = slot >> 7;               // 0..3
            int idx  = slot & 127;
            int m    = idx >> 1;                // 0..63
            int kv   = (idx & 1) * 4;           // 0 or 4
            float4 v;
            if (tile == 3) {
                int j = j0 + m;
                v = (j < CC) ? *(const float4*)&W[(size_t)j*AD + k0 + kv]
                             : make_float4(0.f, 0.f, 0.f, 0.f);
                sB[kv+0][m] = v.x; sB[kv+1][m] = v.y; sB[kv+2][m] = v.z; sB[kv+3][m] = v.w;
            } else {
                const float* src = (tile == 0) ? F : (tile == 1 ? g_cvn : g_wcv);
                v = *(const float4*)&src[(size_t)(i0 + m)*AD + k0 + kv];
                if (tile == 0)      { sF [kv+0][m]=v.x; sF [kv+1][m]=v.y; sF [kv+2][m]=v.z; sF [kv+3][m]=v.w; }
                else if (tile == 1) { sC [kv+0][m]=v.x; sC [kv+1][m]=v.y; sC [kv+2][m]=v.z; sC [kv+3][m]=v.w; }
                else                { sWc[kv+0][m]=v.x; sWc[kv+1][m]=v.y; sWc[kv+2][m]=v.z; sWc[kv+3][m]=v.w; }
            }
        }
        __syncthreads();
        #pragma unroll
        for (int kk = 0; kk < BK; kk++) {
            float4 b4 = *(float4*)&sB[kk][tx*4];
            float4 f4 = *(float4*)&sF[kk][ty*4];
            float4 c4 = *(float4*)&sC[kk][ty*4];
            float4 w4 = *(float4*)&sWc[kk][ty*4];
            float bb[4]  = {b4.x, b4.y, b4.z, b4.w};
            float bsq[4] = {b4.x*b4.x, b4.y*b4.y, b4.z*b4.z, b4.w*b4.w};
            float ff[4]  = {f4.x, f4.y, f4.z, f4.w};
            float cc[4]  = {c4.x, c4.y, c4.z, c4.w};
            float ww[4]  = {w4.x, w4.y, w4.z, w4.w};
            #pragma unroll
            for (int r = 0; r < 4; r++) {
                #pragma unroll
                for (int c = 0; c < 4; c++) {
                    ay[r][c] = fmaf(ff[r], bb[c],  ay[r][c]);
                    a1[r][c] = fmaf(cc[r], bsq[c], a1[r][c]);
                    a2[r][c] = fmaf(ww[r], bb[c],  a2[r][c]);
                }
            }
        }
    }

    // ratio: robust to int or float bit patterns
    int bits = *ratio_bits;
    float ratio = (bits & 0x7f800000) ? __int_as_float(bits) : (float)bits;

    #pragma unroll
    for (int r = 0; r < 4; r++) {
        int i = i0 + ty*4 + r;
        float t3 = g_t3[i];
        #pragma unroll
        for (int c = 0; c < 4; c++) {
            int j = j0 + tx*4 + c;
            if (j < CC) {
                float y = ay[r][c] + bias[j];
                d_out[OFF_Y + (size_t)i*CC + j] = y;
                g_isda[(size_t)i*CC + j] = y + 0.5f * ratio * (a1[r][c] - 2.f*a2[r][c] + t3);
            }
        }
    }
}

// ------------------------------------------------- log-softmax + NLL loss
__global__ void k_loss(const int* __restrict__ labels, float* __restrict__ d_out) {
    __shared__ float sh[256];
    int i = blockIdx.x;
    const float* row = g_isda + (size_t)i * CC;
    float m = -INFINITY;
    for (int j = threadIdx.x; j < CC; j += 256) m = fmaxf(m, row[j]);
    sh[threadIdx.x] = m;
    __syncthreads();
    for (int s = 128; s > 0; s >>= 1) {
        if (threadIdx.x < s) sh[threadIdx.x] = fmaxf(sh[threadIdx.x], sh[threadIdx.x + s]);
        __syncthreads();
    }
    float mx = sh[0];
    __syncthreads();
    float acc = 0.f;
    for (int j = threadIdx.x; j < CC; j += 256) acc += expf(row[j] - mx);
    sh[threadIdx.x] = acc;
    __syncthreads();
    for (int s = 128; s > 0; s >>= 1) {
        if (threadIdx.x < s) sh[threadIdx.x] += sh[threadIdx.x + s];
        __syncthreads();
    }
    if (threadIdx.x == 0) {
        float lp = row[labels[i]] - mx - logf(sh[0]);
        atomicAdd(d_out, -lp * (1.0f / (float)NS));
    }
}

// ---------------------------------------------------------------- launcher
extern "C" void kernel_launch(void* const* d_in, const int* in_sizes, int n_in,
                              void* d_out, int out_size) {
    const float* features = (const float*)d_in[0];
    const int*   labels   = (const int*)  d_in[1];
    const float* fc_w     = (const float*)d_in[2];
    const float* fc_b     = (const float*)d_in[3];
    const float* ave_in   = (const float*)d_in[4];
    const float* cov_in   = (const float*)d_in[5];
    const float* amt_in   = (const float*)d_in[6];
    const int*   ratio_p  = (const int*)  d_in[7];
    float* out = (float*)d_out;

    const int ZB = (CC*AD + 255) / 256;   // 8000
    k_zero<<<ZB, 256>>>(out);
    k_sums<<<NS, 256>>>(features, labels);
    k_ave<<<ZB, 256>>>();
    k_sq<<<NS, 256>>>(features, labels);
    k_fin<<<ZB, 256>>>(ave_in, cov_in, amt_in, out);
    k_gather<<<NS, 256>>>(fc_w, labels);
    dim3 grid((CC + BN - 1) / BN, NS / BM);   // 16 x 8
    k_gemm<<<grid, 256>>>(features, fc_w, fc_b, ratio_p, out);
    k_loss<<<NS, 256>>>(labels, out);
}

// round 4
// speedup vs baseline: 3.7246x; 3.7246x over previous
#include <cuda_runtime.h>
#include <cuda_bf16.h>
#include <cstdint>
#include <math.h>

// Problem sizes (fixed by setup_inputs)
#define NS 512     // samples
#define AD 2048    // feature dim
#define CC 1000    // classes
#define CP 1024    // classes padded to N-tile multiple

// Output layout: loss(1) | y | new_ave | new_cov | new_amount
#define OFF_Y    1
#define OFF_AVE  (1 + NS*CC)
#define OFF_COV  (OFF_AVE + CC*AD)
#define OFF_AMT  (OFF_COV + CC*AD)

// ---------------------------------------------------------------- scratch
__device__ float g_counts[CC];
__device__ float g_sums[CC*AD];   // raw per-class sums
__device__ float g_sq[CC*AD];     // sq-diff sums; after k_fin: new_cov (aligned)
__device__ float g_t3[NS];
__device__ float g_isda[NS*CC];
__device__ __nv_bfloat16 g_fhi[NS*AD], g_flo[NS*AD];     // bf16 split of F
__device__ __nv_bfloat16 g_cvb[NS*AD], g_wcb[NS*AD];     // bf16 cv_n, -2*w_n*cv_n
__device__ __nv_bfloat16 g_whi[CP*AD], g_wlo[CP*AD], g_wsq[CP*AD]; // W split + W^2, padded

// ================================================================ PTX utils
__device__ __forceinline__ uint32_t smem_u32(const void* p) {
    uint32_t a;
    asm("{ .reg .u64 t; cvta.to.shared.u64 t, %1; cvt.u32.u64 %0, t; }" : "=r"(a) : "l"(p));
    return a;
}
#define SWZ(o) ((o) ^ (((o) >> 3) & 0x70))

__device__ __forceinline__ void cp16(uint32_t dst, const void* src) {
    asm volatile("cp.async.cg.shared.global [%0], [%1], 16;" :: "r"(dst), "l"(src) : "memory");
}
#define CP_COMMIT() asm volatile("cp.async.commit_group;" ::: "memory")
template <int N> __device__ __forceinline__ void cp_wait() {
    asm volatile("cp.async.wait_group %0;" :: "n"(N) : "memory");
}
__device__ __forceinline__ void ldsm_x4(uint32_t addr, uint32_t* r) {
    asm volatile("ldmatrix.sync.aligned.m8n8.x4.shared.b16 {%0,%1,%2,%3}, [%4];"
        : "=r"(r[0]), "=r"(r[1]), "=r"(r[2]), "=r"(r[3]) : "r"(addr));
}
__device__ __forceinline__ void mma_bf16(float* d, const uint32_t* a, const uint32_t* b) {
    asm volatile("mma.sync.aligned.m16n8k16.row.col.f32.bf16.bf16.f32 "
        "{%0,%1,%2,%3}, {%4,%5,%6,%7}, {%8,%9}, {%0,%1,%2,%3};"
        : "+f"(d[0]), "+f"(d[1]), "+f"(d[2]), "+f"(d[3])
        : "r"(a[0]), "r"(a[1]), "r"(a[2]), "r"(a[3]), "r"(b[0]), "r"(b[1]));
}

// ================================================================ stats
__global__ void k_zero(float* d_out) {
    long gid = (long)blockIdx.x * blockDim.x + threadIdx.x;
    if (gid < (long)CC*AD) { g_sums[gid] = 0.f; g_sq[gid] = 0.f; }
    if (gid < CC) g_counts[gid] = 0.f;
    if (gid == 0) d_out[0] = 0.f;
}

__global__ void k_sums(const float* __restrict__ f, const int* __restrict__ labels) {
    int i = blockIdx.x;
    int l = labels[i];
    if (threadIdx.x == 0) atomicAdd(&g_counts[l], 1.0f);
    const float4* fr = (const float4*)(f + (size_t)i * AD);
    float* dst = g_sums + (size_t)l * AD;
    for (int v = threadIdx.x; v < AD/4; v += blockDim.x) {
        float4 x = fr[v];
        atomicAdd(dst + 4*v + 0, x.x);
        atomicAdd(dst + 4*v + 1, x.y);
        atomicAdd(dst + 4*v + 2, x.z);
        atomicAdd(dst + 4*v + 3, x.w);
    }
}

// squared-diff segment sum (ave computed on the fly from raw sums)
__global__ void k_sq(const float* __restrict__ f, const int* __restrict__ labels) {
    int i = blockIdx.x;
    int l = labels[i];
    float cnt = g_counts[l];
    float den = (cnt == 0.f) ? 1.f : cnt;
    const float4* fr = (const float4*)(f + (size_t)i * AD);
    const float4* sr = (const float4*)(g_sums + (size_t)l * AD);
    float* dst = g_sq + (size_t)l * AD;
    for (int v = threadIdx.x; v < AD/4; v += blockDim.x) {
        float4 x = fr[v];
        float4 s = sr[v];
        float dx = x.x - s.x/den, dy = x.y - s.y/den, dz = x.z - s.z/den, dw = x.w - s.w/den;
        atomicAdd(dst + 4*v + 0, dx*dx);
        atomicAdd(dst + 4*v + 1, dy*dy);
        atomicAdd(dst + 4*v + 2, dz*dz);
        atomicAdd(dst + 4*v + 3, dw*dw);
    }
}

// finalize ave/cov/amount; new_cov also kept in g_sq (aligned) for gather
__global__ void k_fin(const float* __restrict__ ave_in, const float* __restrict__ cov_in,
                      const float* __restrict__ amt_in, float* __restrict__ d_out) {
    long gid = (long)blockIdx.x * blockDim.x + threadIdx.x;
    if (gid >= (long)CC*AD) return;
    int c = (int)(gid / AD);
    float cnt = g_counts[c];
    float amt = amt_in[c];
    float den = cnt + amt;
    float w = (den > 0.f) ? (cnt / den) : 0.f;
    float vden = (cnt == 0.f) ? 1.f : cnt;
    float aveC = g_sums[gid] / vden;
    float var  = g_sq[gid] / vden;
    float a0   = ave_in[gid];
    float c0   = cov_in[gid];
    float d    = a0 - aveC;
    float addl = w * (1.f - w) * d * d;
    float ncov = c0 * (1.f - w) + var * w + addl;
    d_out[OFF_COV + gid] = ncov;
    g_sq[gid] = ncov;
    d_out[OFF_AVE + gid] = a0 * (1.f - w) + aveC * w;
    if (gid < CC) d_out[OFF_AMT + gid] = amt_in[gid] + g_counts[gid];
}

// gather cv_n (bf16), -2*w_n*cv_n (bf16), t3 (fp32)
__global__ void k_gather(const float* __restrict__ W, const int* __restrict__ labels) {
    __shared__ float sh[256];
    int i = blockIdx.x;
    int l = labels[i];
    const float* cvr = g_sq + (size_t)l * AD;
    const float* wr  = W + (size_t)l * AD;
    float acc = 0.f;
    for (int a = threadIdx.x; a < AD; a += 256) {
        float cv = cvr[a];
        float w  = wr[a];
        g_cvb[(size_t)i*AD + a] = __float2bfloat16(cv);
        g_wcb[(size_t)i*AD + a] = __float2bfloat16(-2.f * w * cv);
        acc += w * w * cv;
    }
    sh[threadIdx.x] = acc;
    __syncthreads();
    for (int s = 128; s > 0; s >>= 1) {
        if (threadIdx.x < s) sh[threadIdx.x] += sh[threadIdx.x + s];
        __syncthreads();
    }
    if (threadIdx.x == 0) g_t3[i] = sh[0];
}

// F -> bf16 split
__global__ void k_fconv(const float* __restrict__ F) {
    int idx = blockIdx.x * blockDim.x + threadIdx.x;
    if (idx >= NS*AD) return;
    float f = F[idx];
    __nv_bfloat16 hi = __float2bfloat16(f);
    g_fhi[idx] = hi;
    g_flo[idx] = __float2bfloat16(f - __bfloat162float(hi));
}

// W -> bf16 split + W^2, padded rows [1000,1024) = 0
__global__ void k_wconv(const float* __restrict__ W) {
    int idx = blockIdx.x * blockDim.x + threadIdx.x;
    if (idx >= CP*AD) return;
    int row = idx / AD, col = idx - row*AD;
    float w = (row < CC) ? W[(size_t)row*AD + col] : 0.f;
    __nv_bfloat16 hi = __float2bfloat16(w);
    g_whi[idx] = hi;
    g_wlo[idx] = __float2bfloat16(w - __bfloat162float(hi));
    g_wsq[idx] = __float2bfloat16(w * w);
}

// ================================================================ HMMA GEMM
// CTA tile 64(M) x 64(N), K chunk 64 (128B rows), double buffered.
// 8 warps: 2(M) x 4(N); each warp 32x16 output, 5 mma products fused.
#define TM 64
#define TN 64
#define KC 64
#define KITERS (AD/KC)              // 32
#define MAT_BYTES (64*128)          // 8192 per matrix per stage
#define STAGE_BYTES (7*MAT_BYTES)   // 57344
#define GEMM_SMEM (2*STAGE_BYTES)   // 114688

__device__ __forceinline__ void load_stage(uint32_t stg, int k0, int i0, int j0, int tid) {
    const __nv_bfloat16* As[4] = {g_fhi, g_flo, g_cvb, g_wcb};
    const __nv_bfloat16* Bs[3] = {g_whi, g_wlo, g_wsq};
    #pragma unroll
    for (int q = 0; q < 14; q++) {
        int id = tid + q*256;
        int m = (id >> 9) & 7;          // matrix index within A(0-3) or B(0-2)
        int idx = id & 511;
        int r = idx >> 3, c = idx & 7;
        if (id < 2048) {                // A: 4 mats x 64 rows x 8 chunks
            const __nv_bfloat16* src = As[m] + (size_t)(i0 + r)*AD + k0 + c*8;
            cp16(stg + m*MAT_BYTES + SWZ(r*128 + c*16), src);
        } else {                        // B: 3 mats x 64 rows x 8 chunks
            m = (id - 2048) >> 9;
            const __nv_bfloat16* src = Bs[m] + (size_t)(j0 + r)*AD + k0 + c*8;
            cp16(stg + (4+m)*MAT_BYTES + SWZ(r*128 + c*16), src);
        }
    }
}

__global__ __launch_bounds__(256, 1) void k_gemm_mma(
    const float* __restrict__ bias, const int* __restrict__ ratio_bits,
    float* __restrict__ d_out)
{
    extern __shared__ char smem[];
    uint32_t sb = smem_u32(smem);
    int tid = threadIdx.x, wid = tid >> 5, lane = tid & 31;
    int mw = wid & 1, nw = wid >> 1;               // 2 x 4 warp grid
    int i0 = blockIdx.y * TM, j0 = blockIdx.x * TN;

    float accY[2][2][4] = {};   // [mt][nt][frag]
    float accT[2][2][4] = {};

    uint32_t stg0 = sb, stg1 = sb + STAGE_BYTES;
    load_stage(stg0, 0,  i0, j0, tid); CP_COMMIT();
    load_stage(stg1, KC, i0, j0, tid); CP_COMMIT();

    for (int it = 0; it < KITERS; ++it) {
        uint32_t stg = (it & 1) ? stg1 : stg0;
        if (it == KITERS - 1) cp_wait<0>(); else cp_wait<1>();
        __syncthreads();

        #pragma unroll
        for (int ks = 0; ks < 4; ks++) {
            // A fragments: 4 matrices x 2 m-tiles
            uint32_t a[4][2][4];
            int arow = mw*32 + (lane & 15);
            int akb  = ks*32 + ((lane >> 4) << 4);
            #pragma unroll
            for (int m = 0; m < 4; m++) {
                #pragma unroll
                for (int mt = 0; mt < 2; mt++) {
                    uint32_t addr = stg + m*MAT_BYTES + SWZ((arow + mt*16)*128 + akb);
                    ldsm_x4(addr, a[m][mt]);
                }
            }
            // B fragments: 3 matrices, 16 n-cols each (x4 -> two n-tiles of 2 regs)
            uint32_t b[3][4];
            int brow = nw*16 + ((lane >> 4) << 3) + (lane & 7);
            int bkb  = ks*32 + (((lane >> 3) & 1) << 4);
            #pragma unroll
            for (int m = 0; m < 3; m++) {
                uint32_t addr = stg + (4+m)*MAT_BYTES + SWZ(brow*128 + bkb);
                ldsm_x4(addr, b[m]);
            }
            #pragma unroll
            for (int mt = 0; mt < 2; mt++) {
                #pragma unroll
                for (int nt = 0; nt < 2; nt++) {
                    const uint32_t* bw = &b[0][nt*2];
                    const uint32_t* bl = &b[1][nt*2];
                    const uint32_t* bs = &b[2][nt*2];
                    mma_bf16(accY[mt][nt], a[0][mt], bw);   // Fhi*Whi
                    mma_bf16(accY[mt][nt], a[0][mt], bl);   // Fhi*Wlo
                    mma_bf16(accY[mt][nt], a[1][mt], bw);   // Flo*Whi
                    mma_bf16(accT[mt][nt], a[2][mt], bs);   // cv*W^2   (t1)
                    mma_bf16(accT[mt][nt], a[3][mt], bw);   // -2wcv*W  (-2*t2)
                }
            }
        }
        __syncthreads();
        if (it + 2 < KITERS) {
            load_stage(stg, (it + 2)*KC, i0, j0, tid);
            CP_COMMIT();
        }
    }

    // epilogue: direct from registers
    int bits = *ratio_bits;
    float ratio = (bits & 0x7f800000) ? __int_as_float(bits) : (float)bits;
    #pragma unroll
    for (int mt = 0; mt < 2; mt++) {
        #pragma unroll
        for (int half = 0; half < 2; half++) {
            int i = i0 + mw*32 + mt*16 + (lane >> 2) + half*8;
            float t3v = g_t3[i];
            #pragma unroll
            for (int nt = 0; nt < 2; nt++) {
                #pragma unroll
                for (int c2 = 0; c2 < 2; c2++) {
                    int j = j0 + nw*16 + nt*8 + (lane & 3)*2 + c2;
                    if (j < CC) {
                        float yv = accY[mt][nt][half*2 + c2] + bias[j];
                        d_out[OFF_Y + (size_t)i*CC + j] = yv;
                        g_isda[(size_t)i*CC + j] =
                            yv + 0.5f * ratio * (accT[mt][nt][half*2 + c2] + t3v);
                    }
                }
            }
        }
    }
}

// ================================================================ loss
__global__ void k_loss(const int* __restrict__ labels, float* __restrict__ d_out) {
    __shared__ float sh[256];
    int i = blockIdx.x;
    const float* row = g_isda + (size_t)i * CC;
    float m = -INFINITY;
    for (int j = threadIdx.x; j < CC; j += 256) m = fmaxf(m, row[j]);
    sh[threadIdx.x] = m;
    __syncthreads();
    for (int s = 128; s > 0; s >>= 1) {
        if (threadIdx.x < s) sh[threadIdx.x] = fmaxf(sh[threadIdx.x], sh[threadIdx.x + s]);
        __syncthreads();
    }
    float mx = sh[0];
    __syncthreads();
    float acc = 0.f;
    for (int j = threadIdx.x; j < CC; j += 256) acc += expf(row[j] - mx);
    sh[threadIdx.x] = acc;
    __syncthreads();
    for (int s = 128; s > 0; s >>= 1) {
        if (threadIdx.x < s) sh[threadIdx.x] += sh[threadIdx.x + s];
        __syncthreads();
    }
    if (threadIdx.x == 0) {
        float lp = row[labels[i]] - mx - logf(sh[0]);
        atomicAdd(d_out, -lp * (1.0f / (float)NS));
    }
}

// ================================================================ launcher
extern "C" void kernel_launch(void* const* d_in, const int* in_sizes, int n_in,
                              void* d_out, int out_size) {
    const float* features = (const float*)d_in[0];
    const int*   labels   = (const int*)  d_in[1];
    const float* fc_w     = (const float*)d_in[2];
    const float* fc_b     = (const float*)d_in[3];
    const float* ave_in   = (const float*)d_in[4];
    const float* cov_in   = (const float*)d_in[5];
    const float* amt_in   = (const float*)d_in[6];
    const int*   ratio_p  = (const int*)  d_in[7];
    float* out = (float*)d_out;

    cudaFuncSetAttribute(k_gemm_mma, cudaFuncAttributeMaxDynamicSharedMemorySize, GEMM_SMEM);

    const int ZB = (CC*AD + 255) / 256;   // 8000
    k_zero<<<ZB, 256>>>(out);
    k_sums<<<NS, 256>>>(features, labels);
    k_sq<<<NS, 256>>>(features, labels);
    k_fin<<<ZB, 256>>>(ave_in, cov_in, amt_in, out);
    k_fconv<<<(NS*AD + 255)/256, 256>>>(features);
    k_wconv<<<(CP*AD + 255)/256, 256>>>(fc_w);
    k_gather<<<NS, 256>>>(fc_w, labels);
    dim3 grid(CP / TN, NS / TM);          // 16 x 8 = 128 CTAs
    k_gemm_mma<<<grid, 256, GEMM_SMEM>>>(fc_b, ratio_p, out);
    k_loss<<<NS, 256>>>(labels, out);
}

// round 5
// speedup vs baseline: 4.8505x; 1.3023x over previous
#include <cuda_runtime.h>
#include <cuda_bf16.h>
#include <cstdint>
#include <math.h>

// Problem sizes (fixed by setup_inputs)
#define NS 512     // samples
#define AD 2048    // feature dim
#define CC 1000    // classes
#define CP 1024    // classes padded to N-tile multiple

// Output layout: loss(1) | y | new_ave | new_cov | new_amount
#define OFF_Y    1
#define OFF_AVE  (1 + NS*CC)
#define OFF_COV  (OFF_AVE + CC*AD)
#define OFF_AMT  (OFF_COV + CC*AD)

// ---------------------------------------------------------------- scratch
__device__ int   g_csr_start[CC+1];
__device__ int   g_csr_idx[NS];
__device__ int   g_fill[CC];
__device__ float g_sq[CC*AD];     // new_cov, 16B-aligned copy for gather
__device__ float g_t3[NS];
__device__ float g_isda[NS*CC];
__device__ __nv_bfloat16 g_fhi[NS*AD], g_flo[NS*AD];     // bf16 split of F
__device__ __nv_bfloat16 g_cvb[NS*AD], g_wcb[NS*AD];     // bf16 cv_n, -2*w_n*cv_n
__device__ __nv_bfloat16 g_whi[CP*AD], g_wlo[CP*AD], g_wsq[CP*AD]; // W split + W^2, padded

// ================================================================ PTX utils
__device__ __forceinline__ uint32_t smem_u32(const void* p) {
    uint32_t a;
    asm("{ .reg .u64 t; cvta.to.shared.u64 t, %1; cvt.u32.u64 %0, t; }" : "=r"(a) : "l"(p));
    return a;
}
#define SWZ(o) ((o) ^ (((o) >> 3) & 0x70))

__device__ __forceinline__ void cp16(uint32_t dst, const void* src) {
    asm volatile("cp.async.cg.shared.global [%0], [%1], 16;" :: "r"(dst), "l"(src) : "memory");
}
#define CP_COMMIT() asm volatile("cp.async.commit_group;" ::: "memory")
template <int N> __device__ __forceinline__ void cp_wait() {
    asm volatile("cp.async.wait_group %0;" :: "n"(N) : "memory");
}
__device__ __forceinline__ void ldsm_x4(uint32_t addr, uint32_t* r) {
    asm volatile("ldmatrix.sync.aligned.m8n8.x4.shared.b16 {%0,%1,%2,%3}, [%4];"
        : "=r"(r[0]), "=r"(r[1]), "=r"(r[2]), "=r"(r[3]) : "r"(addr));
}
__device__ __forceinline__ void mma_bf16(float* d, const uint32_t* a, const uint32_t* b) {
    asm volatile("mma.sync.aligned.m16n8k16.row.col.f32.bf16.bf16.f32 "
        "{%0,%1,%2,%3}, {%4,%5,%6,%7}, {%8,%9}, {%0,%1,%2,%3};"
        : "+f"(d[0]), "+f"(d[1]), "+f"(d[2]), "+f"(d[3])
        : "r"(a[0]), "r"(a[1]), "r"(a[2]), "r"(a[3]), "r"(b[0]), "r"(b[1]));
}

// ================================================================ CSR prep
// counts -> prefix sum -> sample index list; also zeros d_out[0]
__global__ __launch_bounds__(1024) void k_prep(const int* __restrict__ labels,
                                               float* __restrict__ d_out) {
    __shared__ int sh[1024];
    __shared__ int cnts[CC];
    int t = threadIdx.x;
    if (t < CC) cnts[t] = 0;
    __syncthreads();
    if (t < NS) atomicAdd(&cnts[labels[t]], 1);
    __syncthreads();
    sh[t] = (t < CC) ? cnts[t] : 0;
    __syncthreads();
    for (int off = 1; off < 1024; off <<= 1) {
        int v = (t >= off) ? sh[t - off] : 0;
        __syncthreads();
        sh[t] += v;
        __syncthreads();
    }
    if (t < CC) {
        int start = (t == 0) ? 0 : sh[t-1];
        g_csr_start[t] = start;
        g_fill[t] = start;
        if (t == CC-1) g_csr_start[CC] = sh[t];
    }
    __syncthreads();
    if (t < NS) {
        int l = labels[t];
        int pos = atomicAdd(&g_fill[l], 1);
        g_csr_idx[pos] = t;
    }
    if (t == 0) d_out[0] = 0.f;
}

// ================================================================ fused stats + finalize
// One block per class. cnt==0 -> copy-through. Else gather its samples directly.
__global__ __launch_bounds__(256) void k_fin2(
    const float* __restrict__ F,
    const float* __restrict__ ave_in, const float* __restrict__ cov_in,
    const float* __restrict__ amt_in, float* __restrict__ d_out)
{
    int c = blockIdx.x;
    int t = threadIdx.x;
    int start = g_csr_start[c], end = g_csr_start[c+1];
    int cnt = end - start;
    float fcnt = (float)cnt;
    float amt = amt_in[c];
    float dsum = fcnt + amt;
    float w = (dsum > 0.f) ? (fcnt / dsum) : 0.f;
    float omw = 1.f - w;
    size_t base = (size_t)c * AD;

    if (t == 0) d_out[OFF_AMT + c] = amt + fcnt;

    const float4* av4 = (const float4*)(ave_in + base);
    const float4* cv4 = (const float4*)(cov_in + base);
    float4* sq4 = (float4*)(g_sq + base);

    if (cnt == 0) {
        // w = 0: new_cov = cov_in, new_ave = ave_in
        #pragma unroll
        for (int h = 0; h < 2; h++) {
            int v = t + h*256;
            float4 a = av4[v];
            float4 cvv = cv4[v];
            sq4[v] = cvv;
            long o = base + 4l*v;
            d_out[OFF_AVE + o + 0] = a.x; d_out[OFF_AVE + o + 1] = a.y;
            d_out[OFF_AVE + o + 2] = a.z; d_out[OFF_AVE + o + 3] = a.w;
            d_out[OFF_COV + o + 0] = cvv.x; d_out[OFF_COV + o + 1] = cvv.y;
            d_out[OFF_COV + o + 2] = cvv.z; d_out[OFF_COV + o + 3] = cvv.w;
        }
        return;
    }

    float inv = 1.f / fcnt;
    #pragma unroll
    for (int h = 0; h < 2; h++) {
        int v = t + h*256;
        // pass 1: mean
        float4 s = make_float4(0.f, 0.f, 0.f, 0.f);
        for (int p = start; p < end; p++) {
            const float4* fr = (const float4*)(F + (size_t)g_csr_idx[p] * AD);
            float4 x = fr[v];
            s.x += x.x; s.y += x.y; s.z += x.z; s.w += x.w;
        }
        float4 mean = make_float4(s.x*inv, s.y*inv, s.z*inv, s.w*inv);
        // pass 2: var (F rows hit L1)
        float4 q = make_float4(0.f, 0.f, 0.f, 0.f);
        for (int p = start; p < end; p++) {
            const float4* fr = (const float4*)(F + (size_t)g_csr_idx[p] * AD);
            float4 x = fr[v];
            float dx = x.x-mean.x, dy = x.y-mean.y, dz = x.z-mean.z, dw = x.w-mean.w;
            q.x += dx*dx; q.y += dy*dy; q.z += dz*dz; q.w += dw*dw;
        }
        float4 a = av4[v];
        float4 c0 = cv4[v];
        float4 ncov, nave;
        {
            float d0 = a.x - mean.x, d1 = a.y - mean.y, d2 = a.z - mean.z, d3 = a.w - mean.w;
            float ww = w * omw;
            ncov.x = c0.x*omw + q.x*inv*w + ww*d0*d0;
            ncov.y = c0.y*omw + q.y*inv*w + ww*d1*d1;
            ncov.z = c0.z*omw + q.z*inv*w + ww*d2*d2;
            ncov.w = c0.w*omw + q.w*inv*w + ww*d3*d3;
            nave.x = a.x*omw + mean.x*w;
            nave.y = a.y*omw + mean.y*w;
            nave.z = a.z*omw + mean.z*w;
            nave.w = a.w*omw + mean.w*w;
        }
        sq4[v] = ncov;
        long o = base + 4l*v;
        d_out[OFF_AVE + o + 0] = nave.x; d_out[OFF_AVE + o + 1] = nave.y;
        d_out[OFF_AVE + o + 2] = nave.z; d_out[OFF_AVE + o + 3] = nave.w;
        d_out[OFF_COV + o + 0] = ncov.x; d_out[OFF_COV + o + 1] = ncov.y;
        d_out[OFF_COV + o + 2] = ncov.z; d_out[OFF_COV + o + 3] = ncov.w;
    }
}

// gather cv_n (bf16), -2*w_n*cv_n (bf16), t3 (fp32) — vectorized
__global__ __launch_bounds__(256) void k_gather(const float* __restrict__ W,
                                                const int* __restrict__ labels) {
    __shared__ float sh[256];
    int i = blockIdx.x;
    int l = labels[i];
    const float4* cvr = (const float4*)(g_sq + (size_t)l * AD);
    const float4* wr  = (const float4*)(W + (size_t)l * AD);
    __nv_bfloat162* cvd = (__nv_bfloat162*)(g_cvb + (size_t)i * AD);
    __nv_bfloat162* wcd = (__nv_bfloat162*)(g_wcb + (size_t)i * AD);
    float acc = 0.f;
    #pragma unroll
    for (int h = 0; h < 2; h++) {
        int v = threadIdx.x + h*256;
        float4 cv = cvr[v];
        float4 w  = wr[v];
        cvd[2*v+0] = __floats2bfloat162_rn(cv.x, cv.y);
        cvd[2*v+1] = __floats2bfloat162_rn(cv.z, cv.w);
        wcd[2*v+0] = __floats2bfloat162_rn(-2.f*w.x*cv.x, -2.f*w.y*cv.y);
        wcd[2*v+1] = __floats2bfloat162_rn(-2.f*w.z*cv.z, -2.f*w.w*cv.w);
        acc += w.x*w.x*cv.x + w.y*w.y*cv.y + w.z*w.z*cv.z + w.w*w.w*cv.w;
    }
    sh[threadIdx.x] = acc;
    __syncthreads();
    for (int s = 128; s > 0; s >>= 1) {
        if (threadIdx.x < s) sh[threadIdx.x] += sh[threadIdx.x + s];
        __syncthreads();
    }
    if (threadIdx.x == 0) g_t3[i] = sh[0];
}

// F -> bf16 split (float4 vectorized)
__global__ void k_fconv(const float* __restrict__ F) {
    int v = blockIdx.x * blockDim.x + threadIdx.x;
    if (v >= NS*AD/4) return;
    float4 f = ((const float4*)F)[v];
    float hx = __bfloat162float(__float2bfloat16(f.x));
    float hy = __bfloat162float(__float2bfloat16(f.y));
    float hz = __bfloat162float(__float2bfloat16(f.z));
    float hw = __bfloat162float(__float2bfloat16(f.w));
    __nv_bfloat162* hi = (__nv_bfloat162*)g_fhi;
    __nv_bfloat162* lo = (__nv_bfloat162*)g_flo;
    hi[2*v+0] = __floats2bfloat162_rn(hx, hy);
    hi[2*v+1] = __floats2bfloat162_rn(hz, hw);
    lo[2*v+0] = __floats2bfloat162_rn(f.x - hx, f.y - hy);
    lo[2*v+1] = __floats2bfloat162_rn(f.z - hz, f.w - hw);
}

// W -> bf16 split + W^2, padded rows [1000,1024) = 0 (float4 vectorized)
__global__ void k_wconv(const float* __restrict__ W) {
    int v = blockIdx.x * blockDim.x + threadIdx.x;
    if (v >= CP*AD/4) return;
    int row = (v*4) / AD;
    float4 f;
    if (row < CC) f = ((const float4*)W)[v - (size_t)0];   // same linear index (CC rows first)
    else          f = make_float4(0.f, 0.f, 0.f, 0.f);
    float hx = __bfloat162float(__float2bfloat16(f.x));
    float hy = __bfloat162float(__float2bfloat16(f.y));
    float hz = __bfloat162float(__float2bfloat16(f.z));
    float hw = __bfloat162float(__float2bfloat16(f.w));
    __nv_bfloat162* hi = (__nv_bfloat162*)g_whi;
    __nv_bfloat162* lo = (__nv_bfloat162*)g_wlo;
    __nv_bfloat162* sq = (__nv_bfloat162*)g_wsq;
    hi[2*v+0] = __floats2bfloat162_rn(hx, hy);
    hi[2*v+1] = __floats2bfloat162_rn(hz, hw);
    lo[2*v+0] = __floats2bfloat162_rn(f.x - hx, f.y - hy);
    lo[2*v+1] = __floats2bfloat162_rn(f.z - hz, f.w - hw);
    sq[2*v+0] = __floats2bfloat162_rn(f.x*f.x, f.y*f.y);
    sq[2*v+1] = __floats2bfloat162_rn(f.z*f.z, f.w*f.w);
}

// ================================================================ HMMA GEMM
// CTA tile 64(M) x 64(N), K chunk 64 (128B rows), double buffered.
// 8 warps: 2(M) x 4(N); each warp 32x16 output, 5 mma products fused.
#define TM 64
#define TN 64
#define KC 64
#define KITERS (AD/KC)              // 32
#define MAT_BYTES (64*128)          // 8192 per matrix per stage
#define STAGE_BYTES (7*MAT_BYTES)   // 57344
#define GEMM_SMEM (2*STAGE_BYTES)   // 114688

__device__ __forceinline__ void load_stage(uint32_t stg, int k0, int i0, int j0, int tid) {
    const __nv_bfloat16* As[4] = {g_fhi, g_flo, g_cvb, g_wcb};
    const __nv_bfloat16* Bs[3] = {g_whi, g_wlo, g_wsq};
    #pragma unroll
    for (int q = 0; q < 14; q++) {
        int id = tid + q*256;
        int m = (id >> 9) & 7;
        int idx = id & 511;
        int r = idx >> 3, c = idx & 7;
        if (id < 2048) {
            const __nv_bfloat16* src = As[m] + (size_t)(i0 + r)*AD + k0 + c*8;
            cp16(stg + m*MAT_BYTES + SWZ(r*128 + c*16), src);
        } else {
            m = (id - 2048) >> 9;
            const __nv_bfloat16* src = Bs[m] + (size_t)(j0 + r)*AD + k0 + c*8;
            cp16(stg + (4+m)*MAT_BYTES + SWZ(r*128 + c*16), src);
        }
    }
}

__global__ __launch_bounds__(256, 1) void k_gemm_mma(
    const float* __restrict__ bias, const int* __restrict__ ratio_bits,
    float* __restrict__ d_out)
{
    extern __shared__ char smem[];
    uint32_t sb = smem_u32(smem);
    int tid = threadIdx.x, wid = tid >> 5, lane = tid & 31;
    int mw = wid & 1, nw = wid >> 1;               // 2 x 4 warp grid
    int i0 = blockIdx.y * TM, j0 = blockIdx.x * TN;

    float accY[2][2][4] = {};   // [mt][nt][frag]
    float accT[2][2][4] = {};

    uint32_t stg0 = sb, stg1 = sb + STAGE_BYTES;
    load_stage(stg0, 0,  i0, j0, tid); CP_COMMIT();
    load_stage(stg1, KC, i0, j0, tid); CP_COMMIT();

    for (int it = 0; it < KITERS; ++it) {
        uint32_t stg = (it & 1) ? stg1 : stg0;
        if (it == KITERS - 1) cp_wait<0>(); else cp_wait<1>();
        __syncthreads();

        #pragma unroll
        for (int ks = 0; ks < 4; ks++) {
            uint32_t a[4][2][4];
            int arow = mw*32 + (lane & 15);
            int akb  = ks*32 + ((lane >> 4) << 4);
            #pragma unroll
            for (int m = 0; m < 4; m++) {
                #pragma unroll
                for (int mt = 0; mt < 2; mt++) {
                    uint32_t addr = stg + m*MAT_BYTES + SWZ((arow + mt*16)*128 + akb);
                    ldsm_x4(addr, a[m][mt]);
                }
            }
            uint32_t b[3][4];
            int brow = nw*16 + ((lane >> 4) << 3) + (lane & 7);
            int bkb  = ks*32 + (((lane >> 3) & 1) << 4);
            #pragma unroll
            for (int m = 0; m < 3; m++) {
                uint32_t addr = stg + (4+m)*MAT_BYTES + SWZ(brow*128 + bkb);
                ldsm_x4(addr, b[m]);
            }
            #pragma unroll
            for (int mt = 0; mt < 2; mt++) {
                #pragma unroll
                for (int nt = 0; nt < 2; nt++) {
                    const uint32_t* bw = &b[0][nt*2];
                    const uint32_t* bl = &b[1][nt*2];
                    const uint32_t* bs = &b[2][nt*2];
                    mma_bf16(accY[mt][nt], a[0][mt], bw);   // Fhi*Whi
                    mma_bf16(accY[mt][nt], a[0][mt], bl);   // Fhi*Wlo
                    mma_bf16(accY[mt][nt], a[1][mt], bw);   // Flo*Whi
                    mma_bf16(accT[mt][nt], a[2][mt], bs);   // cv*W^2   (t1)
                    mma_bf16(accT[mt][nt], a[3][mt], bw);   // -2wcv*W  (-2*t2)
                }
            }
        }
        __syncthreads();
        if (it + 2 < KITERS) {
            load_stage(stg, (it + 2)*KC, i0, j0, tid);
            CP_COMMIT();
        }
    }

    int bits = *ratio_bits;
    float ratio = (bits & 0x7f800000) ? __int_as_float(bits) : (float)bits;
    #pragma unroll
    for (int mt = 0; mt < 2; mt++) {
        #pragma unroll
        for (int half = 0; half < 2; half++) {
            int i = i0 + mw*32 + mt*16 + (lane >> 2) + half*8;
            float t3v = g_t3[i];
            #pragma unroll
            for (int nt = 0; nt < 2; nt++) {
                #pragma unroll
                for (int c2 = 0; c2 < 2; c2++) {
                    int j = j0 + nw*16 + nt*8 + (lane & 3)*2 + c2;
                    if (j < CC) {
                        float yv = accY[mt][nt][half*2 + c2] + bias[j];
                        d_out[OFF_Y + (size_t)i*CC + j] = yv;
                        g_isda[(size_t)i*CC + j] =
                            yv + 0.5f * ratio * (accT[mt][nt][half*2 + c2] + t3v);
                    }
                }
            }
        }
    }
}

// ================================================================ loss
__global__ void k_loss(const int* __restrict__ labels, float* __restrict__ d_out) {
    __shared__ float sh[256];
    int i = blockIdx.x;
    const float* row = g_isda + (size_t)i * CC;
    float m = -INFINITY;
    for (int j = threadIdx.x; j < CC; j += 256) m = fmaxf(m, row[j]);
    sh[threadIdx.x] = m;
    __syncthreads();
    for (int s = 128; s > 0; s >>= 1) {
        if (threadIdx.x < s) sh[threadIdx.x] = fmaxf(sh[threadIdx.x], sh[threadIdx.x + s]);
        __syncthreads();
    }
    float mx = sh[0];
    __syncthreads();
    float acc = 0.f;
    for (int j = threadIdx.x; j < CC; j += 256) acc += expf(row[j] - mx);
    sh[threadIdx.x] = acc;
    __syncthreads();
    for (int s = 128; s > 0; s >>= 1) {
        if (threadIdx.x < s) sh[threadIdx.x] += sh[threadIdx.x + s];
        __syncthreads();
    }
    if (threadIdx.x == 0) {
        float lp = row[labels[i]] - mx - logf(sh[0]);
        atomicAdd(d_out, -lp * (1.0f / (float)NS));
    }
}

// ================================================================ launcher
extern "C" void kernel_launch(void* const* d_in, const int* in_sizes, int n_in,
                              void* d_out, int out_size) {
    const float* features = (const float*)d_in[0];
    const int*   labels   = (const int*)  d_in[1];
    const float* fc_w     = (const float*)d_in[2];
    const float* fc_b     = (const float*)d_in[3];
    const float* ave_in   = (const float*)d_in[4];
    const float* cov_in   = (const float*)d_in[5];
    const float* amt_in   = (const float*)d_in[6];
    const int*   ratio_p  = (const int*)  d_in[7];
    float* out = (float*)d_out;

    cudaFuncSetAttribute(k_gemm_mma, cudaFuncAttributeMaxDynamicSharedMemorySize, GEMM_SMEM);

    k_prep<<<1, 1024>>>(labels, out);
    k_fconv<<<(NS*AD/4 + 255)/256, 256>>>(features);
    k_wconv<<<(CP*AD/4 + 255)/256, 256>>>(fc_w);
    k_fin2<<<CC, 256>>>(features, ave_in, cov_in, amt_in, out);
    k_gather<<<NS, 256>>>(fc_w, labels);
    dim3 grid(CP / TN, NS / TM);          // 16 x 8 = 128 CTAs
    k_gemm_mma<<<grid, 256, GEMM_SMEM>>>(fc_b, ratio_p, out);
    k_loss<<<NS, 256>>>(labels, out);
}

// round 6
// speedup vs baseline: 5.4618x; 1.1260x over previous
#include <cuda_runtime.h>
#include <cuda_bf16.h>
#include <cstdint>
#include <math.h>

// Problem sizes (fixed by setup_inputs)
#define NS 512     // samples
#define AD 2048    // feature dim
#define CC 1000    // classes
#define CP 1024    // classes padded to N-tile multiple

// Output layout: loss(1) | y | new_ave | new_cov | new_amount
#define OFF_Y    1
#define OFF_AVE  (1 + NS*CC)
#define OFF_COV  (OFF_AVE + CC*AD)
#define OFF_AMT  (OFF_COV + CC*AD)

// ---------------------------------------------------------------- scratch
__device__ int   g_csr_start[CC+1];
__device__ int   g_csr_idx[NS];
__device__ int   g_fill[CC];
__device__ float g_t3[NS];
__device__ float g_isda[NS*CC];
__device__ __nv_bfloat16 g_fhi[NS*AD], g_flo[NS*AD];     // bf16 split of F
__device__ __nv_bfloat16 g_cvb[NS*AD], g_wcb[NS*AD];     // bf16 cv_n, -2*w_n*cv_n
__device__ __nv_bfloat16 g_whi[CP*AD], g_wlo[CP*AD], g_wsq[CP*AD]; // W split + W^2, padded

// ================================================================ PTX utils
__device__ __forceinline__ uint32_t smem_u32(const void* p) {
    uint32_t a;
    asm("{ .reg .u64 t; cvta.to.shared.u64 t, %1; cvt.u32.u64 %0, t; }" : "=r"(a) : "l"(p));
    return a;
}
#define SWZ(o) ((o) ^ (((o) >> 3) & 0x70))

__device__ __forceinline__ void cp16(uint32_t dst, const void* src) {
    asm volatile("cp.async.cg.shared.global [%0], [%1], 16;" :: "r"(dst), "l"(src) : "memory");
}
#define CP_COMMIT() asm volatile("cp.async.commit_group;" ::: "memory")
template <int N> __device__ __forceinline__ void cp_wait() {
    asm volatile("cp.async.wait_group %0;" :: "n"(N) : "memory");
}
__device__ __forceinline__ void ldsm_x4(uint32_t addr, uint32_t* r) {
    asm volatile("ldmatrix.sync.aligned.m8n8.x4.shared.b16 {%0,%1,%2,%3}, [%4];"
        : "=r"(r[0]), "=r"(r[1]), "=r"(r[2]), "=r"(r[3]) : "r"(addr));
}
__device__ __forceinline__ void mma_bf16(float* d, const uint32_t* a, const uint32_t* b) {
    asm volatile("mma.sync.aligned.m16n8k16.row.col.f32.bf16.bf16.f32 "
        "{%0,%1,%2,%3}, {%4,%5,%6,%7}, {%8,%9}, {%0,%1,%2,%3};"
        : "+f"(d[0]), "+f"(d[1]), "+f"(d[2]), "+f"(d[3])
        : "r"(a[0]), "r"(a[1]), "r"(a[2]), "r"(a[3]), "r"(b[0]), "r"(b[1]));
}

// ================================================================ k_pre
// block 0: CSR prep (counts -> prefix -> index list), zero loss slot
// blocks 1..: F bf16 split + W bf16 split + W^2 conversion
#define FCONV_ITEMS (NS*AD/4)          // 262144 float4
#define WCONV_ITEMS (CP*AD/4)          // 524288 float4
#define CONV_BLOCKS ((FCONV_ITEMS + WCONV_ITEMS + 1023) / 1024)   // 768

__global__ __launch_bounds__(1024) void k_pre(
    const float* __restrict__ F, const float* __restrict__ W,
    const int* __restrict__ labels, float* __restrict__ d_out)
{
    int t = threadIdx.x;
    if (blockIdx.x == 0) {
        __shared__ int sh[1024];
        __shared__ int cnts[CC];
        if (t < CC) cnts[t] = 0;
        __syncthreads();
        if (t < NS) atomicAdd(&cnts[labels[t]], 1);
        __syncthreads();
        sh[t] = (t < CC) ? cnts[t] : 0;
        __syncthreads();
        for (int off = 1; off < 1024; off <<= 1) {
            int v = (t >= off) ? sh[t - off] : 0;
            __syncthreads();
            sh[t] += v;
            __syncthreads();
        }
        if (t < CC) {
            int start = (t == 0) ? 0 : sh[t-1];
            g_csr_start[t] = start;
            g_fill[t] = start;
            if (t == CC-1) g_csr_start[CC] = sh[t];
        }
        __syncthreads();
        if (t < NS) {
            int l = labels[t];
            int pos = atomicAdd(&g_fill[l], 1);
            g_csr_idx[pos] = t;
        }
        if (t == 0) d_out[0] = 0.f;
        return;
    }
    int id = (blockIdx.x - 1) * 1024 + t;
    if (id < FCONV_ITEMS) {
        float4 f = ((const float4*)F)[id];
        float hx = __bfloat162float(__float2bfloat16(f.x));
        float hy = __bfloat162float(__float2bfloat16(f.y));
        float hz = __bfloat162float(__float2bfloat16(f.z));
        float hw = __bfloat162float(__float2bfloat16(f.w));
        __nv_bfloat162* hi = (__nv_bfloat162*)g_fhi;
        __nv_bfloat162* lo = (__nv_bfloat162*)g_flo;
        hi[2*id+0] = __floats2bfloat162_rn(hx, hy);
        hi[2*id+1] = __floats2bfloat162_rn(hz, hw);
        lo[2*id+0] = __floats2bfloat162_rn(f.x - hx, f.y - hy);
        lo[2*id+1] = __floats2bfloat162_rn(f.z - hz, f.w - hw);
    } else {
        int v = id - FCONV_ITEMS;
        if (v >= WCONV_ITEMS) return;
        int row = (v*4) / AD;
        float4 f = (row < CC) ? ((const float4*)W)[v] : make_float4(0.f, 0.f, 0.f, 0.f);
        float hx = __bfloat162float(__float2bfloat16(f.x));
        float hy = __bfloat162float(__float2bfloat16(f.y));
        float hz = __bfloat162float(__float2bfloat16(f.z));
        float hw = __bfloat162float(__float2bfloat16(f.w));
        __nv_bfloat162* hi = (__nv_bfloat162*)g_whi;
        __nv_bfloat162* lo = (__nv_bfloat162*)g_wlo;
        __nv_bfloat162* sq = (__nv_bfloat162*)g_wsq;
        hi[2*v+0] = __floats2bfloat162_rn(hx, hy);
        hi[2*v+1] = __floats2bfloat162_rn(hz, hw);
        lo[2*v+0] = __floats2bfloat162_rn(f.x - hx, f.y - hy);
        lo[2*v+1] = __floats2bfloat162_rn(f.z - hz, f.w - hw);
        sq[2*v+0] = __floats2bfloat162_rn(f.x*f.x, f.y*f.y);
        sq[2*v+1] = __floats2bfloat162_rn(f.z*f.z, f.w*f.w);
    }
}

// ================================================================ k_mid
// blocks [0, CC):       finalize ave/cov/amount for class c -> d_out
// blocks [CC, CC+NS):   per-sample gather: recompute new_cov for own label,
//                       emit bf16 cv_n, -2*w_n*cv_n, and t3
__device__ __forceinline__ void class_stats(
    const float* __restrict__ F, int start, int end, float inv, int v,
    float4& mean, float4& q)
{
    float4 s = make_float4(0.f, 0.f, 0.f, 0.f);
    for (int p = start; p < end; p++) {
        const float4* fr = (const float4*)(F + (size_t)g_csr_idx[p] * AD);
        float4 x = fr[v];
        s.x += x.x; s.y += x.y; s.z += x.z; s.w += x.w;
    }
    mean = make_float4(s.x*inv, s.y*inv, s.z*inv, s.w*inv);
    q = make_float4(0.f, 0.f, 0.f, 0.f);
    for (int p = start; p < end; p++) {
        const float4* fr = (const float4*)(F + (size_t)g_csr_idx[p] * AD);
        float4 x = fr[v];
        float dx = x.x-mean.x, dy = x.y-mean.y, dz = x.z-mean.z, dw = x.w-mean.w;
        q.x += dx*dx; q.y += dy*dy; q.z += dz*dz; q.w += dw*dw;
    }
}

__global__ __launch_bounds__(256) void k_mid(
    const float* __restrict__ F, const float* __restrict__ W,
    const int* __restrict__ labels,
    const float* __restrict__ ave_in, const float* __restrict__ cov_in,
    const float* __restrict__ amt_in, float* __restrict__ d_out)
{
    int t = threadIdx.x;
    if (blockIdx.x < CC) {
        // ---- finalize class c
        int c = blockIdx.x;
        int start = g_csr_start[c], end = g_csr_start[c+1];
        int cnt = end - start;
        float fcnt = (float)cnt;
        float amt = amt_in[c];
        float dsum = fcnt + amt;
        float w = (dsum > 0.f) ? (fcnt / dsum) : 0.f;
        float omw = 1.f - w;
        size_t base = (size_t)c * AD;
        if (t == 0) d_out[OFF_AMT + c] = amt + fcnt;

        const float4* av4 = (const float4*)(ave_in + base);
        const float4* cv4 = (const float4*)(cov_in + base);

        if (cnt == 0) {
            #pragma unroll
            for (int h = 0; h < 2; h++) {
                int v = t + h*256;
                float4 a = av4[v];
                float4 cvv = cv4[v];
                long o = base + 4l*v;
                d_out[OFF_AVE + o + 0] = a.x; d_out[OFF_AVE + o + 1] = a.y;
                d_out[OFF_AVE + o + 2] = a.z; d_out[OFF_AVE + o + 3] = a.w;
                d_out[OFF_COV + o + 0] = cvv.x; d_out[OFF_COV + o + 1] = cvv.y;
                d_out[OFF_COV + o + 2] = cvv.z; d_out[OFF_COV + o + 3] = cvv.w;
            }
            return;
        }
        float inv = 1.f / fcnt;
        #pragma unroll
        for (int h = 0; h < 2; h++) {
            int v = t + h*256;
            float4 mean, q;
            class_stats(F, start, end, inv, v, mean, q);
            float4 a = av4[v];
            float4 c0 = cv4[v];
            float ww = w * omw;
            float d0 = a.x - mean.x, d1 = a.y - mean.y, d2 = a.z - mean.z, d3 = a.w - mean.w;
            float ncx = c0.x*omw + q.x*inv*w + ww*d0*d0;
            float ncy = c0.y*omw + q.y*inv*w + ww*d1*d1;
            float ncz = c0.z*omw + q.z*inv*w + ww*d2*d2;
            float ncw = c0.w*omw + q.w*inv*w + ww*d3*d3;
            long o = base + 4l*v;
            d_out[OFF_AVE + o + 0] = a.x*omw + mean.x*w;
            d_out[OFF_AVE + o + 1] = a.y*omw + mean.y*w;
            d_out[OFF_AVE + o + 2] = a.z*omw + mean.z*w;
            d_out[OFF_AVE + o + 3] = a.w*omw + mean.w*w;
            d_out[OFF_COV + o + 0] = ncx; d_out[OFF_COV + o + 1] = ncy;
            d_out[OFF_COV + o + 2] = ncz; d_out[OFF_COV + o + 3] = ncw;
        }
    } else {
        // ---- gather for sample i (recompute own class new_cov; L1/L2 hot)
        __shared__ float sh[256];
        int i = blockIdx.x - CC;
        int l = labels[i];
        int start = g_csr_start[l], end = g_csr_start[l+1];
        float fcnt = (float)(end - start);         // >= 1
        float amt = amt_in[l];
        float w = fcnt / (fcnt + amt);
        float omw = 1.f - w;
        float inv = 1.f / fcnt;
        size_t base = (size_t)l * AD;
        const float4* av4 = (const float4*)(ave_in + base);
        const float4* cv4 = (const float4*)(cov_in + base);
        const float4* wr  = (const float4*)(W + base);
        __nv_bfloat162* cvd = (__nv_bfloat162*)(g_cvb + (size_t)i * AD);
        __nv_bfloat162* wcd = (__nv_bfloat162*)(g_wcb + (size_t)i * AD);
        float acc = 0.f;
        #pragma unroll
        for (int h = 0; h < 2; h++) {
            int v = t + h*256;
            float4 mean, q;
            class_stats(F, start, end, inv, v, mean, q);
            float4 a = av4[v];
            float4 c0 = cv4[v];
            float ww = w * omw;
            float d0 = a.x - mean.x, d1 = a.y - mean.y, d2 = a.z - mean.z, d3 = a.w - mean.w;
            float4 nc;
            nc.x = c0.x*omw + q.x*inv*w + ww*d0*d0;
            nc.y = c0.y*omw + q.y*inv*w + ww*d1*d1;
            nc.z = c0.z*omw + q.z*inv*w + ww*d2*d2;
            nc.w = c0.w*omw + q.w*inv*w + ww*d3*d3;
            float4 wf = wr[v];
            cvd[2*v+0] = __floats2bfloat162_rn(nc.x, nc.y);
            cvd[2*v+1] = __floats2bfloat162_rn(nc.z, nc.w);
            wcd[2*v+0] = __floats2bfloat162_rn(-2.f*wf.x*nc.x, -2.f*wf.y*nc.y);
            wcd[2*v+1] = __floats2bfloat162_rn(-2.f*wf.z*nc.z, -2.f*wf.w*nc.w);
            acc += wf.x*wf.x*nc.x + wf.y*wf.y*nc.y + wf.z*wf.z*nc.z + wf.w*wf.w*nc.w;
        }
        sh[t] = acc;
        __syncthreads();
        for (int s = 128; s > 0; s >>= 1) {
            if (t < s) sh[t] += sh[t + s];
            __syncthreads();
        }
        if (t == 0) g_t3[i] = sh[0];
    }
}

// ================================================================ HMMA GEMM
// CTA tile 64(M) x 64(N), K chunk 64 (128B rows), double buffered.
// 8 warps: 2(M) x 4(N); each warp 32x16 output, 5 mma products fused.
#define TM 64
#define TN 64
#define KC 64
#define KITERS (AD/KC)              // 32
#define MAT_BYTES (64*128)          // 8192 per matrix per stage
#define STAGE_BYTES (7*MAT_BYTES)   // 57344
#define GEMM_SMEM (2*STAGE_BYTES)   // 114688

__device__ __forceinline__ void load_stage(uint32_t stg, int k0, int i0, int j0, int tid) {
    const __nv_bfloat16* As[4] = {g_fhi, g_flo, g_cvb, g_wcb};
    const __nv_bfloat16* Bs[3] = {g_whi, g_wlo, g_wsq};
    #pragma unroll
    for (int q = 0; q < 14; q++) {
        int id = tid + q*256;
        int m = (id >> 9) & 7;
        int idx = id & 511;
        int r = idx >> 3, c = idx & 7;
        if (id < 2048) {
            const __nv_bfloat16* src = As[m] + (size_t)(i0 + r)*AD + k0 + c*8;
            cp16(stg + m*MAT_BYTES + SWZ(r*128 + c*16), src);
        } else {
            m = (id - 2048) >> 9;
            const __nv_bfloat16* src = Bs[m] + (size_t)(j0 + r)*AD + k0 + c*8;
            cp16(stg + (4+m)*MAT_BYTES + SWZ(r*128 + c*16), src);
        }
    }
}

__global__ __launch_bounds__(256, 1) void k_gemm_mma(
    const float* __restrict__ bias, const int* __restrict__ ratio_bits,
    float* __restrict__ d_out)
{
    extern __shared__ char smem[];
    uint32_t sb = smem_u32(smem);
    int tid = threadIdx.x, wid = tid >> 5, lane = tid & 31;
    int mw = wid & 1, nw = wid >> 1;               // 2 x 4 warp grid
    int i0 = blockIdx.y * TM, j0 = blockIdx.x * TN;

    float accY[2][2][4] = {};   // [mt][nt][frag]
    float accT[2][2][4] = {};

    uint32_t stg0 = sb, stg1 = sb + STAGE_BYTES;
    load_stage(stg0, 0,  i0, j0, tid); CP_COMMIT();
    load_stage(stg1, KC, i0, j0, tid); CP_COMMIT();

    for (int it = 0; it < KITERS; ++it) {
        uint32_t stg = (it & 1) ? stg1 : stg0;
        if (it == KITERS - 1) cp_wait<0>(); else cp_wait<1>();
        __syncthreads();

        #pragma unroll
        for (int ks = 0; ks < 4; ks++) {
            uint32_t a[4][2][4];
            int arow = mw*32 + (lane & 15);
            int akb  = ks*32 + ((lane >> 4) << 4);
            #pragma unroll
            for (int m = 0; m < 4; m++) {
                #pragma unroll
                for (int mt = 0; mt < 2; mt++) {
                    uint32_t addr = stg + m*MAT_BYTES + SWZ((arow + mt*16)*128 + akb);
                    ldsm_x4(addr, a[m][mt]);
                }
            }
            uint32_t b[3][4];
            int brow = nw*16 + ((lane >> 4) << 3) + (lane & 7);
            int bkb  = ks*32 + (((lane >> 3) & 1) << 4);
            #pragma unroll
            for (int m = 0; m < 3; m++) {
                uint32_t addr = stg + (4+m)*MAT_BYTES + SWZ(brow*128 + bkb);
                ldsm_x4(addr, b[m]);
            }
            #pragma unroll
            for (int mt = 0; mt < 2; mt++) {
                #pragma unroll
                for (int nt = 0; nt < 2; nt++) {
                    const uint32_t* bw = &b[0][nt*2];
                    const uint32_t* bl = &b[1][nt*2];
                    const uint32_t* bs = &b[2][nt*2];
                    mma_bf16(accY[mt][nt], a[0][mt], bw);   // Fhi*Whi
                    mma_bf16(accY[mt][nt], a[0][mt], bl);   // Fhi*Wlo
                    mma_bf16(accY[mt][nt], a[1][mt], bw);   // Flo*Whi
                    mma_bf16(accT[mt][nt], a[2][mt], bs);   // cv*W^2   (t1)
                    mma_bf16(accT[mt][nt], a[3][mt], bw);   // -2wcv*W  (-2*t2)
                }
            }
        }
        __syncthreads();
        if (it + 2 < KITERS) {
            load_stage(stg, (it + 2)*KC, i0, j0, tid);
            CP_COMMIT();
        }
    }

    int bits = *ratio_bits;
    float ratio = (bits & 0x7f800000) ? __int_as_float(bits) : (float)bits;
    #pragma unroll
    for (int mt = 0; mt < 2; mt++) {
        #pragma unroll
        for (int half = 0; half < 2; half++) {
            int i = i0 + mw*32 + mt*16 + (lane >> 2) + half*8;
            float t3v = g_t3[i];
            #pragma unroll
            for (int nt = 0; nt < 2; nt++) {
                #pragma unroll
                for (int c2 = 0; c2 < 2; c2++) {
                    int j = j0 + nw*16 + nt*8 + (lane & 3)*2 + c2;
                    if (j < CC) {
                        float yv = accY[mt][nt][half*2 + c2] + bias[j];
                        d_out[OFF_Y + (size_t)i*CC + j] = yv;
                        g_isda[(size_t)i*CC + j] =
                            yv + 0.5f * ratio * (accT[mt][nt][half*2 + c2] + t3v);
                    }
                }
            }
        }
    }
}

// ================================================================ loss
__global__ void k_loss(const int* __restrict__ labels, float* __restrict__ d_out) {
    __shared__ float sh[256];
    int i = blockIdx.x;
    const float* row = g_isda + (size_t)i * CC;
    float m = -INFINITY;
    for (int j = threadIdx.x; j < CC; j += 256) m = fmaxf(m, row[j]);
    sh[threadIdx.x] = m;
    __syncthreads();
    for (int s = 128; s > 0; s >>= 1) {
        if (threadIdx.x < s) sh[threadIdx.x] = fmaxf(sh[threadIdx.x], sh[threadIdx.x + s]);
        __syncthreads();
    }
    float mx = sh[0];
    __syncthreads();
    float acc = 0.f;
    for (int j = threadIdx.x; j < CC; j += 256) acc += __expf(row[j] - mx);
    sh[threadIdx.x] = acc;
    __syncthreads();
    for (int s = 128; s > 0; s >>= 1) {
        if (threadIdx.x < s) sh[threadIdx.x] += sh[threadIdx.x + s];
        __syncthreads();
    }
    if (threadIdx.x == 0) {
        float lp = row[labels[i]] - mx - logf(sh[0]);
        atomicAdd(d_out, -lp * (1.0f / (float)NS));
    }
}

// ================================================================ launcher
extern "C" void kernel_launch(void* const* d_in, const int* in_sizes, int n_in,
                              void* d_out, int out_size) {
    const float* features = (const float*)d_in[0];
    const int*   labels   = (const int*)  d_in[1];
    const float* fc_w     = (const float*)d_in[2];
    const float* fc_b     = (const float*)d_in[3];
    const float* ave_in   = (const float*)d_in[4];
    const float* cov_in   = (const float*)d_in[5];
    const float* amt_in   = (const float*)d_in[6];
    const int*   ratio_p  = (const int*)  d_in[7];
    float* out = (float*)d_out;

    cudaFuncSetAttribute(k_gemm_mma, cudaFuncAttributeMaxDynamicSharedMemorySize, GEMM_SMEM);

    k_pre<<<1 + CONV_BLOCKS, 1024>>>(features, fc_w, labels, out);
    k_mid<<<CC + NS, 256>>>(features, fc_w, labels, ave_in, cov_in, amt_in, out);
    dim3 grid(CP / TN, NS / TM);          // 16 x 8 = 128 CTAs
    k_gemm_mma<<<grid, 256, GEMM_SMEM>>>(fc_b, ratio_p, out);
    k_loss<<<NS, 256>>>(labels, out);
}